// round 3
// baseline (speedup 1.0000x reference)
#include <cuda_runtime.h>

// Problem constants (fixed by the reference)
#define NN   50000
#define NE   800000
#define DIN  128
#define DHID 128
#define DOUT 64

// ---------------------------------------------------------------------------
// Static device scratch (no allocation allowed)
// ---------------------------------------------------------------------------
__device__ int    g_is64;                     // 1 if edge_index is int64
__device__ int    g_deg[NN];
__device__ int    g_cur[NN];
__device__ int    g_rowptr[NN + 1];
__device__ int    g_csrc[NE];                 // CSR: src node per incoming edge
__device__ float  g_dinv[NN];                 // rsqrt(1 + in_degree)
__device__ float4 g_t4[NN * DHID / 4];        // transform buffer (t = h @ W)
__device__ float4 g_h4[NN * DHID / 4];        // aggregation buffer

// ---------------------------------------------------------------------------
// Edge-index dtype detection + accessor
// ---------------------------------------------------------------------------
__global__ void detect_kernel(const void* __restrict__ ei) {
    // Interpret the first 64 entries as int64. True int64 indices are all in
    // [0, NN). int32 data reinterpreted as int64 yields values >= 2^32 unless
    // the odd word happens to be 0 (p ~ 1e-5 per entry).
    const long long* p = (const long long*)ei;
    int ok = 1;
    for (int i = 0; i < 64; i++) {
        long long v = p[i];
        if (v < 0 || v >= NN) { ok = 0; break; }
    }
    g_is64 = ok;
}

__device__ __forceinline__ int edge_at(const void* ei, int is64, int pos) {
    if (is64) return (int)((const long long*)ei)[pos];
    return ((const int*)ei)[pos];
}

// ---------------------------------------------------------------------------
// CSR construction
// ---------------------------------------------------------------------------
__global__ void zero_kernel() {
    int i = blockIdx.x * blockDim.x + threadIdx.x;
    if (i < NN) { g_deg[i] = 0; g_cur[i] = 0; }
}

__global__ void deg_count_kernel(const void* __restrict__ ei) {
    int e = blockIdx.x * blockDim.x + threadIdx.x;
    int is64 = g_is64;
    if (e < NE) {
        int dst = edge_at(ei, is64, NE + e);
        atomicAdd(&g_deg[dst], 1);
    }
}

// Single-block exclusive prefix scan of g_deg -> g_rowptr  (shuffle-based)
__global__ void scan_kernel() {
    __shared__ int wsum[32];
    __shared__ int carry;
    const int tid = threadIdx.x, lane = tid & 31, w = tid >> 5;
    if (tid == 0) carry = 0;
    __syncthreads();

    for (int base = 0; base < NN; base += 1024) {
        int i = base + tid;
        int v = (i < NN) ? g_deg[i] : 0;
        int inc = v;
        #pragma unroll
        for (int o = 1; o < 32; o <<= 1) {
            int n = __shfl_up_sync(0xffffffffu, inc, o);
            if (lane >= o) inc += n;
        }
        if (lane == 31) wsum[w] = inc;
        __syncthreads();
        if (w == 0) {
            int s = wsum[lane];
            #pragma unroll
            for (int o = 1; o < 32; o <<= 1) {
                int n = __shfl_up_sync(0xffffffffu, s, o);
                if (lane >= o) s += n;
            }
            wsum[lane] = s;   // inclusive scan of warp sums
        }
        __syncthreads();
        int woff = (w == 0) ? 0 : wsum[w - 1];
        if (i < NN) g_rowptr[i] = carry + woff + inc - v;   // exclusive
        __syncthreads();
        if (tid == 0) carry += wsum[31];
        __syncthreads();
    }
    if (threadIdx.x == 0) g_rowptr[NN] = carry;
}

__global__ void fill_kernel(const void* __restrict__ ei) {
    int e = blockIdx.x * blockDim.x + threadIdx.x;
    int is64 = g_is64;
    if (e < NE) {
        int src = edge_at(ei, is64, e);
        int dst = edge_at(ei, is64, NE + e);
        int pos = g_rowptr[dst] + atomicAdd(&g_cur[dst], 1);
        g_csrc[pos] = src;
    }
}

__global__ void dinv_kernel() {
    int i = blockIdx.x * blockDim.x + threadIdx.x;
    if (i < NN) g_dinv[i] = rsqrtf(1.0f + (float)g_deg[i]);
}

// ---------------------------------------------------------------------------
// GEMM: Y[M, DO] = X[M, K] @ W[K, DO]  (+ bias if BIAS)
// Block = 64 rows x full DO, 256 threads, W + X tile fully in SMEM.
// ---------------------------------------------------------------------------
template <int K, int DO, bool BIAS>
__global__ void gemm_kernel(const float* __restrict__ X,
                            const float* __restrict__ W,
                            const float* __restrict__ bias,
                            float* __restrict__ Y, int M) {
    extern __shared__ float sm[];
    float* Ws = sm;            // K * DO
    float* Xs = sm + K * DO;   // 64 * K

    const int tid = threadIdx.x;
    const int bm  = blockIdx.x * 64;

    #pragma unroll 4
    for (int i = tid; i < K * DO / 4; i += 256)
        ((float4*)Ws)[i] = ((const float4*)W)[i];

    #pragma unroll 4
    for (int i = tid; i < 64 * K / 4; i += 256) {
        int row  = i / (K / 4);
        int col4 = i % (K / 4);
        float4 v = make_float4(0.f, 0.f, 0.f, 0.f);
        if (bm + row < M)
            v = ((const float4*)(X + (size_t)(bm + row) * K))[col4];
        ((float4*)Xs)[i] = v;
    }
    __syncthreads();

    const int tx = tid & 31;
    const int ty = tid >> 5;           // 0..7
    constexpr int CPT = DO / 32;       // cols per thread

    float acc[8][CPT];
    #pragma unroll
    for (int r = 0; r < 8; r++)
        #pragma unroll
        for (int c = 0; c < CPT; c++) acc[r][c] = 0.f;

    for (int k = 0; k < K; k += 4) {
        float4 xv[8];
        #pragma unroll
        for (int r = 0; r < 8; r++)
            xv[r] = *(const float4*)&Xs[(ty * 8 + r) * K + k];

        #pragma unroll
        for (int kk = 0; kk < 4; kk++) {
            float wv[CPT];
            #pragma unroll
            for (int c = 0; c < CPT; c++)
                wv[c] = Ws[(k + kk) * DO + tx + 32 * c];
            #pragma unroll
            for (int r = 0; r < 8; r++) {
                float xs = (kk == 0) ? xv[r].x : (kk == 1) ? xv[r].y
                         : (kk == 2) ? xv[r].z : xv[r].w;
                #pragma unroll
                for (int c = 0; c < CPT; c++)
                    acc[r][c] = fmaf(xs, wv[c], acc[r][c]);
            }
        }
    }

    #pragma unroll
    for (int r = 0; r < 8; r++) {
        int row = bm + ty * 8 + r;
        if (row < M) {
            #pragma unroll
            for (int c = 0; c < CPT; c++) {
                float v = acc[r][c];
                if (BIAS) v += __ldg(&bias[tx + 32 * c]);
                Y[(size_t)row * DO + tx + 32 * c] = v;
            }
        }
    }
}

// ---------------------------------------------------------------------------
// Gather aggregation (fused self-loop + bias + ReLU):
//   h[i,f] = relu( t[i,f]*dinv[i]^2 + sum_{s in in(i)} t[s,f]*dinv[s]*dinv[i] + b[f] )
// 128 threads/block; NPB nodes per block (D * NPB == 128).
// ---------------------------------------------------------------------------
template <int D, int NPB>
__global__ void gather_kernel(const float* __restrict__ t,
                              const float* __restrict__ bias,
                              float* __restrict__ h) {
    const int node = blockIdx.x * NPB + threadIdx.x / D;
    const int f    = threadIdx.x % D;
    if (node >= NN) return;

    const float di = g_dinv[node];
    float acc = t[(size_t)node * D + f] * di * di;   // self loop

    const int beg = g_rowptr[node];
    const int end = g_rowptr[node + 1];
    for (int e = beg; e < end; e++) {
        int s = __ldg(&g_csrc[e]);
        acc = fmaf(t[(size_t)s * D + f], g_dinv[s] * di, acc);
    }
    acc += __ldg(&bias[f]);
    h[(size_t)node * D + f] = fmaxf(acc, 0.f);
}

// ---------------------------------------------------------------------------
// Launch
// ---------------------------------------------------------------------------
extern "C" void kernel_launch(void* const* d_in, const int* in_sizes, int n_in,
                              void* d_out, int out_size) {
    const float* x   = (const float*)d_in[0];
    const void*  ei  = d_in[1];                  // int32 or int64 (detected)
    const float* W1  = (const float*)d_in[2];
    const float* b1  = (const float*)d_in[3];
    const float* W2  = (const float*)d_in[4];
    const float* b2  = (const float*)d_in[5];
    const float* fcW = (const float*)d_in[6];
    const float* fcb = (const float*)d_in[7];
    float*       out = (float*)d_out;

    float *t_ptr = nullptr, *h_ptr = nullptr;
    cudaGetSymbolAddress((void**)&t_ptr, g_t4);
    cudaGetSymbolAddress((void**)&h_ptr, g_h4);

    constexpr int SM_G1 = (DIN * DHID + 64 * DIN) * 4;    // 96 KB
    constexpr int SM_G2 = (DHID * DOUT + 64 * DHID) * 4;  // 64 KB
    constexpr int SM_G3 = (DOUT * DOUT + 64 * DOUT) * 4;  // 32 KB
    cudaFuncSetAttribute(gemm_kernel<DIN, DHID, false>,
                         cudaFuncAttributeMaxDynamicSharedMemorySize, SM_G1);
    cudaFuncSetAttribute(gemm_kernel<DHID, DOUT, false>,
                         cudaFuncAttributeMaxDynamicSharedMemorySize, SM_G2);
    cudaFuncSetAttribute(gemm_kernel<DOUT, DOUT, true>,
                         cudaFuncAttributeMaxDynamicSharedMemorySize, SM_G3);

    const int TB = 256;
    const int gN    = (NN + TB - 1) / TB;
    const int gE    = (NE + TB - 1) / TB;
    const int gGemm = (NN + 63) / 64;

    // --- dtype detection + CSR build + normalization ---
    detect_kernel<<<1, 1>>>(ei);
    zero_kernel<<<gN, TB>>>();
    deg_count_kernel<<<gE, TB>>>(ei);
    scan_kernel<<<1, 1024>>>();
    fill_kernel<<<gE, TB>>>(ei);
    dinv_kernel<<<gN, TB>>>();

    // --- Layer 1 ---
    gemm_kernel<DIN, DHID, false><<<gGemm, TB, SM_G1>>>(x, W1, nullptr, t_ptr, NN);
    gather_kernel<DHID, 1><<<NN, 128>>>(t_ptr, b1, h_ptr);

    // --- Layer 2 ---
    gemm_kernel<DHID, DOUT, false><<<gGemm, TB, SM_G2>>>(h_ptr, W2, nullptr, t_ptr, NN);
    gather_kernel<DOUT, 2><<<(NN + 1) / 2, 128>>>(t_ptr, b2, h_ptr);

    // --- Final FC ---
    gemm_kernel<DOUT, DOUT, true><<<gGemm, TB, SM_G3>>>(h_ptr, fcW, fcb, out, NN);
}

// round 4
// speedup vs baseline: 1.0270x; 1.0270x over previous
#include <cuda_runtime.h>

// Problem constants (fixed by the reference)
#define NN   50000
#define NE   800000
#define DIN  128
#define DHID 128
#define DOUT 64

#define SCAN_B   256
#define SCAN_G   ((NN + SCAN_B - 1) / SCAN_B)   // 196

// ---------------------------------------------------------------------------
// Static device scratch (no allocation allowed)
// ---------------------------------------------------------------------------
__device__ int    g_is64;                     // 1 if edge_index is int64
__device__ int    g_deg[NN];
__device__ int    g_cur[NN];
__device__ int    g_bsum[SCAN_G];             // per-block sums for scan
__device__ int    g_rowptr[NN + 1];
__device__ int    g_csrc[NE];                 // CSR: src node per incoming edge
__device__ float  g_dinv[NN];                 // rsqrt(1 + in_degree)
__device__ float4 g_t4[NN * DHID / 4];        // transform buffer (t = h @ W)
__device__ float4 g_h4[NN * DHID / 4];        // aggregation buffer

// ---------------------------------------------------------------------------
// Edge-index dtype detection + accessor
// ---------------------------------------------------------------------------
__global__ void detect_kernel(const void* __restrict__ ei) {
    // True int64 indices are all in [0, NN); int32 data reinterpreted as
    // int64 exceeds NN unless the odd word is zero (p ~ 1e-5 per entry).
    const long long* p = (const long long*)ei;
    int ok = 1;
    for (int i = 0; i < 64; i++) {
        long long v = p[i];
        if (v < 0 || v >= NN) { ok = 0; break; }
    }
    g_is64 = ok;
}

__device__ __forceinline__ int edge_at(const void* ei, int is64, int pos) {
    if (is64) return (int)((const long long*)ei)[pos];
    return ((const int*)ei)[pos];
}

// ---------------------------------------------------------------------------
// CSR construction
// ---------------------------------------------------------------------------
__global__ void zero_kernel() {
    int i = blockIdx.x * blockDim.x + threadIdx.x;
    if (i < NN) g_deg[i] = 0;
}

__global__ void deg_count_kernel(const void* __restrict__ ei) {
    int e = blockIdx.x * blockDim.x + threadIdx.x;
    int is64 = g_is64;
    if (e < NE) {
        int dst = edge_at(ei, is64, NE + e);
        atomicAdd(&g_deg[dst], 1);
    }
}

// Pass 1: per-block sums of g_deg
__global__ void scan_partial_kernel() {
    __shared__ int wsum[SCAN_B / 32];
    int i = blockIdx.x * SCAN_B + threadIdx.x;
    int lane = threadIdx.x & 31, w = threadIdx.x >> 5;
    int v = (i < NN) ? g_deg[i] : 0;
    #pragma unroll
    for (int o = 16; o > 0; o >>= 1) v += __shfl_down_sync(0xffffffffu, v, o);
    if (lane == 0) wsum[w] = v;
    __syncthreads();
    if (threadIdx.x == 0) {
        int s = 0;
        #pragma unroll
        for (int k = 0; k < SCAN_B / 32; k++) s += wsum[k];
        g_bsum[blockIdx.x] = s;
    }
}

// Pass 2: exclusive scan of g_bsum (one block; SCAN_G <= 256)
__global__ void scan_bsum_kernel() {
    __shared__ int ws[8];
    int tid = threadIdx.x, lane = tid & 31, w = tid >> 5;
    int v = (tid < SCAN_G) ? g_bsum[tid] : 0;
    int inc = v;
    #pragma unroll
    for (int o = 1; o < 32; o <<= 1) {
        int n = __shfl_up_sync(0xffffffffu, inc, o);
        if (lane >= o) inc += n;
    }
    if (lane == 31) ws[w] = inc;
    __syncthreads();
    if (w == 0 && lane < 8) {
        int s = ws[lane];
        #pragma unroll
        for (int o = 1; o < 8; o <<= 1) {
            int n = __shfl_up_sync(0xffu, s, o);
            if (lane >= o) s += n;
        }
        ws[lane] = s;
    }
    __syncthreads();
    int off = (w == 0) ? 0 : ws[w - 1];
    if (tid < SCAN_G) g_bsum[tid] = off + inc - v;      // exclusive
    if (tid == SCAN_G - 1) g_rowptr[NN] = off + inc;    // total
}

// Pass 3: block-local exclusive scan + block offset; also dinv and g_cur=0
__global__ void scan_final_kernel() {
    __shared__ int wsum[SCAN_B / 32];
    int i = blockIdx.x * SCAN_B + threadIdx.x;
    int lane = threadIdx.x & 31, w = threadIdx.x >> 5;
    int v = (i < NN) ? g_deg[i] : 0;
    int inc = v;
    #pragma unroll
    for (int o = 1; o < 32; o <<= 1) {
        int n = __shfl_up_sync(0xffffffffu, inc, o);
        if (lane >= o) inc += n;
    }
    if (lane == 31) wsum[w] = inc;
    __syncthreads();
    if (w == 0 && lane < SCAN_B / 32) {
        int s = wsum[lane];
        #pragma unroll
        for (int o = 1; o < SCAN_B / 32; o <<= 1) {
            int n = __shfl_up_sync((1u << (SCAN_B / 32)) - 1u, s, o);
            if (lane >= o) s += n;
        }
        wsum[lane] = s;
    }
    __syncthreads();
    int woff = (w == 0) ? 0 : wsum[w - 1];
    if (i < NN) {
        g_rowptr[i] = g_bsum[blockIdx.x] + woff + inc - v;
        g_dinv[i]   = rsqrtf(1.0f + (float)v);
        g_cur[i]    = 0;
    }
}

__global__ void fill_kernel(const void* __restrict__ ei) {
    int e = blockIdx.x * blockDim.x + threadIdx.x;
    int is64 = g_is64;
    if (e < NE) {
        int src = edge_at(ei, is64, e);
        int dst = edge_at(ei, is64, NE + e);
        int pos = g_rowptr[dst] + atomicAdd(&g_cur[dst], 1);
        g_csrc[pos] = src;
    }
}

// ---------------------------------------------------------------------------
// GEMM: Y[M, DO] = X[M, K] @ W[K, DO]  (+ bias if BIAS)
// Block = 64 rows x full DO, 256 threads, W + X tile fully in SMEM.
// ---------------------------------------------------------------------------
template <int K, int DO, bool BIAS>
__global__ void gemm_kernel(const float* __restrict__ X,
                            const float* __restrict__ W,
                            const float* __restrict__ bias,
                            float* __restrict__ Y, int M) {
    extern __shared__ float sm[];
    float* Ws = sm;            // K * DO
    float* Xs = sm + K * DO;   // 64 * K

    const int tid = threadIdx.x;
    const int bm  = blockIdx.x * 64;

    #pragma unroll 4
    for (int i = tid; i < K * DO / 4; i += 256)
        ((float4*)Ws)[i] = ((const float4*)W)[i];

    #pragma unroll 4
    for (int i = tid; i < 64 * K / 4; i += 256) {
        int row  = i / (K / 4);
        int col4 = i % (K / 4);
        float4 v = make_float4(0.f, 0.f, 0.f, 0.f);
        if (bm + row < M)
            v = ((const float4*)(X + (size_t)(bm + row) * K))[col4];
        ((float4*)Xs)[i] = v;
    }
    __syncthreads();

    const int tx = tid & 31;
    const int ty = tid >> 5;           // 0..7
    constexpr int CPT = DO / 32;       // cols per thread

    float acc[8][CPT];
    #pragma unroll
    for (int r = 0; r < 8; r++)
        #pragma unroll
        for (int c = 0; c < CPT; c++) acc[r][c] = 0.f;

    for (int k = 0; k < K; k += 4) {
        float4 xv[8];
        #pragma unroll
        for (int r = 0; r < 8; r++)
            xv[r] = *(const float4*)&Xs[(ty * 8 + r) * K + k];

        #pragma unroll
        for (int kk = 0; kk < 4; kk++) {
            float wv[CPT];
            #pragma unroll
            for (int c = 0; c < CPT; c++)
                wv[c] = Ws[(k + kk) * DO + tx + 32 * c];
            #pragma unroll
            for (int r = 0; r < 8; r++) {
                float xs = (kk == 0) ? xv[r].x : (kk == 1) ? xv[r].y
                         : (kk == 2) ? xv[r].z : xv[r].w;
                #pragma unroll
                for (int c = 0; c < CPT; c++)
                    acc[r][c] = fmaf(xs, wv[c], acc[r][c]);
            }
        }
    }

    #pragma unroll
    for (int r = 0; r < 8; r++) {
        int row = bm + ty * 8 + r;
        if (row < M) {
            #pragma unroll
            for (int c = 0; c < CPT; c++) {
                float v = acc[r][c];
                if (BIAS) v += __ldg(&bias[tx + 32 * c]);
                Y[(size_t)row * DO + tx + 32 * c] = v;
            }
        }
    }
}

// ---------------------------------------------------------------------------
// Gather aggregation (fused self-loop + bias + ReLU):
//   h[i,f] = relu( t[i,f]*dinv[i]^2 + sum_{s in in(i)} t[s,f]*dinv[s]*dinv[i] + b[f] )
// 128 threads/block; NPB nodes per block (D * NPB == 128).
// Edge indices + norms staged cooperatively in SMEM (eliminates redundant
// per-thread broadcast LDGs of csrc/dinv).
// ---------------------------------------------------------------------------
#define EDGE_TILE 128

template <int D, int NPB>
__global__ void gather_kernel(const float* __restrict__ t,
                              const float* __restrict__ bias,
                              float* __restrict__ h) {
    __shared__ int   s_src[NPB][EDGE_TILE];
    __shared__ float s_nrm[NPB][EDGE_TILE];

    const int ln   = threadIdx.x / D;          // local node 0..NPB-1
    const int f    = threadIdx.x % D;
    const int node = blockIdx.x * NPB + ln;
    const bool ok  = (node < NN);

    const float di  = ok ? g_dinv[node] : 0.f;
    const int   beg = ok ? g_rowptr[node] : 0;
    const int   end = ok ? g_rowptr[node + 1] : 0;

    float acc = ok ? t[(size_t)node * D + f] * di * di : 0.f;  // self loop

    for (int base = beg; base < end || __syncthreads_or(0), base < end; base += EDGE_TILE) {
        // (dummy expr keeps form simple; real sync below)
        break;
    }

    // Staged edge loop
    int nTiles = (end - beg + EDGE_TILE - 1) / EDGE_TILE;
    // All node-groups in the block must iterate the same number of tiles for
    // __syncthreads; use the block max.
    __shared__ int s_maxTiles;
    if (threadIdx.x == 0) s_maxTiles = 0;
    __syncthreads();
    if (f == 0) atomicMax(&s_maxTiles, nTiles);
    __syncthreads();
    const int maxTiles = s_maxTiles;

    for (int tile = 0; tile < maxTiles; tile++) {
        int tbeg = beg + tile * EDGE_TILE;
        int cnt  = min(EDGE_TILE, end - tbeg);
        // cooperative stage: the D threads of this node load its edge tile
        for (int j = f; j < cnt; j += D) {
            int s = __ldg(&g_csrc[tbeg + j]);
            s_src[ln][j] = s;
            s_nrm[ln][j] = g_dinv[s] * di;
        }
        __syncthreads();
        int e = 0;
        for (; e + 4 <= cnt; e += 4) {
            int   s0 = s_src[ln][e],     s1 = s_src[ln][e + 1];
            int   s2 = s_src[ln][e + 2], s3 = s_src[ln][e + 3];
            float v0 = t[(size_t)s0 * D + f];
            float v1 = t[(size_t)s1 * D + f];
            float v2 = t[(size_t)s2 * D + f];
            float v3 = t[(size_t)s3 * D + f];
            acc = fmaf(v0, s_nrm[ln][e],     acc);
            acc = fmaf(v1, s_nrm[ln][e + 1], acc);
            acc = fmaf(v2, s_nrm[ln][e + 2], acc);
            acc = fmaf(v3, s_nrm[ln][e + 3], acc);
        }
        for (; e < cnt; e++)
            acc = fmaf(t[(size_t)s_src[ln][e] * D + f], s_nrm[ln][e], acc);
        __syncthreads();
    }

    if (ok) {
        acc += __ldg(&bias[f]);
        h[(size_t)node * D + f] = fmaxf(acc, 0.f);
    }
}

// ---------------------------------------------------------------------------
// Launch
// ---------------------------------------------------------------------------
extern "C" void kernel_launch(void* const* d_in, const int* in_sizes, int n_in,
                              void* d_out, int out_size) {
    const float* x   = (const float*)d_in[0];
    const void*  ei  = d_in[1];                  // int32 or int64 (detected)
    const float* W1  = (const float*)d_in[2];
    const float* b1  = (const float*)d_in[3];
    const float* W2  = (const float*)d_in[4];
    const float* b2  = (const float*)d_in[5];
    const float* fcW = (const float*)d_in[6];
    const float* fcb = (const float*)d_in[7];
    float*       out = (float*)d_out;

    float *t_ptr = nullptr, *h_ptr = nullptr;
    cudaGetSymbolAddress((void**)&t_ptr, g_t4);
    cudaGetSymbolAddress((void**)&h_ptr, g_h4);

    constexpr int SM_G1 = (DIN * DHID + 64 * DIN) * 4;    // 96 KB
    constexpr int SM_G2 = (DHID * DOUT + 64 * DHID) * 4;  // 64 KB
    constexpr int SM_G3 = (DOUT * DOUT + 64 * DOUT) * 4;  // 32 KB
    cudaFuncSetAttribute(gemm_kernel<DIN, DHID, false>,
                         cudaFuncAttributeMaxDynamicSharedMemorySize, SM_G1);
    cudaFuncSetAttribute(gemm_kernel<DHID, DOUT, false>,
                         cudaFuncAttributeMaxDynamicSharedMemorySize, SM_G2);
    cudaFuncSetAttribute(gemm_kernel<DOUT, DOUT, true>,
                         cudaFuncAttributeMaxDynamicSharedMemorySize, SM_G3);

    const int TB = 256;
    const int gN    = (NN + TB - 1) / TB;
    const int gE    = (NE + TB - 1) / TB;
    const int gGemm = (NN + 63) / 64;

    // --- dtype detection + CSR build + normalization ---
    detect_kernel<<<1, 1>>>(ei);
    zero_kernel<<<gN, TB>>>();
    deg_count_kernel<<<gE, TB>>>(ei);
    scan_partial_kernel<<<SCAN_G, SCAN_B>>>();
    scan_bsum_kernel<<<1, 256>>>();
    scan_final_kernel<<<SCAN_G, SCAN_B>>>();
    fill_kernel<<<gE, TB>>>(ei);

    // --- Layer 1 ---
    gemm_kernel<DIN, DHID, false><<<gGemm, TB, SM_G1>>>(x, W1, nullptr, t_ptr, NN);
    gather_kernel<DHID, 1><<<NN, 128>>>(t_ptr, b1, h_ptr);

    // --- Layer 2 ---
    gemm_kernel<DHID, DOUT, false><<<gGemm, TB, SM_G2>>>(h_ptr, W2, nullptr, t_ptr, NN);
    gather_kernel<DOUT, 2><<<(NN + 1) / 2, 128>>>(t_ptr, b2, h_ptr);

    // --- Final FC ---
    gemm_kernel<DOUT, DOUT, true><<<gGemm, TB, SM_G3>>>(h_ptr, fcW, fcb, out, NN);
}

// round 5
// speedup vs baseline: 1.3821x; 1.3457x over previous
#include <cuda_runtime.h>
#include <cuda_fp16.h>

// Problem constants (fixed by the reference)
#define NN   50000
#define NE   800000
#define DIN  128
#define DHID 128
#define DOUT 64

#define SCAN_B   256
#define SCAN_G   ((NN + SCAN_B - 1) / SCAN_B)   // 196

// ---------------------------------------------------------------------------
// Static device scratch (no allocation allowed)
// ---------------------------------------------------------------------------
__device__ int    g_is64;                     // 1 if edge_index is int64
__device__ int    g_deg[NN];
__device__ int    g_cur[NN];
__device__ int    g_bsum[SCAN_G];             // per-block sums for scan
__device__ int    g_rowptr[NN + 1];
__device__ int    g_csrc[NE];                 // CSR: src node per incoming edge
__device__ float  g_dinv[NN];                 // rsqrt(1 + in_degree)
__device__ __half2 g_t2[NN * DHID / 2];       // transform buffer (fp16 pairs)
__device__ float4  g_h4[NN * DHID / 4];       // aggregation buffer (fp32)

// ---------------------------------------------------------------------------
// Edge-index dtype detection + accessor
// ---------------------------------------------------------------------------
__global__ void detect_kernel(const void* __restrict__ ei) {
    // True int64 indices are all in [0, NN); int32 data reinterpreted as
    // int64 exceeds NN unless the odd word is zero (p ~ 1e-5 per entry).
    const long long* p = (const long long*)ei;
    int ok = 1;
    for (int i = 0; i < 64; i++) {
        long long v = p[i];
        if (v < 0 || v >= NN) { ok = 0; break; }
    }
    g_is64 = ok;
}

__device__ __forceinline__ int edge_at(const void* ei, int is64, int pos) {
    if (is64) return (int)((const long long*)ei)[pos];
    return ((const int*)ei)[pos];
}

// ---------------------------------------------------------------------------
// CSR construction
// ---------------------------------------------------------------------------
__global__ void zero_kernel() {
    int i = blockIdx.x * blockDim.x + threadIdx.x;
    if (i < NN) g_deg[i] = 0;
}

__global__ void deg_count_kernel(const void* __restrict__ ei) {
    int e = blockIdx.x * blockDim.x + threadIdx.x;
    int is64 = g_is64;
    if (e < NE) {
        int dst = edge_at(ei, is64, NE + e);
        atomicAdd(&g_deg[dst], 1);
    }
}

// Pass 1: per-block sums of g_deg
__global__ void scan_partial_kernel() {
    __shared__ int wsum[SCAN_B / 32];
    int i = blockIdx.x * SCAN_B + threadIdx.x;
    int lane = threadIdx.x & 31, w = threadIdx.x >> 5;
    int v = (i < NN) ? g_deg[i] : 0;
    #pragma unroll
    for (int o = 16; o > 0; o >>= 1) v += __shfl_down_sync(0xffffffffu, v, o);
    if (lane == 0) wsum[w] = v;
    __syncthreads();
    if (threadIdx.x == 0) {
        int s = 0;
        #pragma unroll
        for (int k = 0; k < SCAN_B / 32; k++) s += wsum[k];
        g_bsum[blockIdx.x] = s;
    }
}

// Pass 2: exclusive scan of g_bsum (one block; SCAN_G <= 256)
__global__ void scan_bsum_kernel() {
    __shared__ int ws[8];
    int tid = threadIdx.x, lane = tid & 31, w = tid >> 5;
    int v = (tid < SCAN_G) ? g_bsum[tid] : 0;
    int inc = v;
    #pragma unroll
    for (int o = 1; o < 32; o <<= 1) {
        int n = __shfl_up_sync(0xffffffffu, inc, o);
        if (lane >= o) inc += n;
    }
    if (lane == 31) ws[w] = inc;
    __syncthreads();
    if (w == 0 && lane < 8) {
        int s = ws[lane];
        #pragma unroll
        for (int o = 1; o < 8; o <<= 1) {
            int n = __shfl_up_sync(0xffu, s, o);
            if (lane >= o) s += n;
        }
        ws[lane] = s;
    }
    __syncthreads();
    int off = (w == 0) ? 0 : ws[w - 1];
    if (tid < SCAN_G) g_bsum[tid] = off + inc - v;      // exclusive
    if (tid == SCAN_G - 1) g_rowptr[NN] = off + inc;    // total
}

// Pass 3: block-local exclusive scan + block offset; also dinv and g_cur=0
__global__ void scan_final_kernel() {
    __shared__ int wsum[SCAN_B / 32];
    int i = blockIdx.x * SCAN_B + threadIdx.x;
    int lane = threadIdx.x & 31, w = threadIdx.x >> 5;
    int v = (i < NN) ? g_deg[i] : 0;
    int inc = v;
    #pragma unroll
    for (int o = 1; o < 32; o <<= 1) {
        int n = __shfl_up_sync(0xffffffffu, inc, o);
        if (lane >= o) inc += n;
    }
    if (lane == 31) wsum[w] = inc;
    __syncthreads();
    if (w == 0 && lane < SCAN_B / 32) {
        int s = wsum[lane];
        #pragma unroll
        for (int o = 1; o < SCAN_B / 32; o <<= 1) {
            int n = __shfl_up_sync((1u << (SCAN_B / 32)) - 1u, s, o);
            if (lane >= o) s += n;
        }
        wsum[lane] = s;
    }
    __syncthreads();
    int woff = (w == 0) ? 0 : wsum[w - 1];
    if (i < NN) {
        g_rowptr[i] = g_bsum[blockIdx.x] + woff + inc - v;
        g_dinv[i]   = rsqrtf(1.0f + (float)v);
        g_cur[i]    = 0;
    }
}

__global__ void fill_kernel(const void* __restrict__ ei) {
    int e = blockIdx.x * blockDim.x + threadIdx.x;
    int is64 = g_is64;
    if (e < NE) {
        int src = edge_at(ei, is64, e);
        int dst = edge_at(ei, is64, NE + e);
        int pos = g_rowptr[dst] + atomicAdd(&g_cur[dst], 1);
        g_csrc[pos] = src;
    }
}

// ---------------------------------------------------------------------------
// GEMM: Y[M, DO] = X[M, K] @ W[K, DO]  (+ bias if BIAS)
// Block = 64 rows x full DO, 256 threads, W + X tile fully in SMEM.
// Thread owns 8 rows x (DO/64) column PAIRS: cols {2tx+64c, 2tx+64c+1}.
// HALF_OUT: store __half2; else float2.
// ---------------------------------------------------------------------------
template <int K, int DO, bool BIAS, bool HALF_OUT>
__global__ void gemm_kernel(const float* __restrict__ X,
                            const float* __restrict__ W,
                            const float* __restrict__ bias,
                            void* __restrict__ Y, int M) {
    extern __shared__ float sm[];
    float* Ws = sm;            // K * DO
    float* Xs = sm + K * DO;   // 64 * K

    const int tid = threadIdx.x;
    const int bm  = blockIdx.x * 64;

    #pragma unroll 4
    for (int i = tid; i < K * DO / 4; i += 256)
        ((float4*)Ws)[i] = ((const float4*)W)[i];

    #pragma unroll 4
    for (int i = tid; i < 64 * K / 4; i += 256) {
        int row  = i / (K / 4);
        int col4 = i % (K / 4);
        float4 v = make_float4(0.f, 0.f, 0.f, 0.f);
        if (bm + row < M)
            v = ((const float4*)(X + (size_t)(bm + row) * K))[col4];
        ((float4*)Xs)[i] = v;
    }
    __syncthreads();

    const int tx = tid & 31;
    const int ty = tid >> 5;           // 0..7
    constexpr int CP2 = DO / 64;       // column pairs per thread

    float2 acc[8][CP2];
    #pragma unroll
    for (int r = 0; r < 8; r++)
        #pragma unroll
        for (int c = 0; c < CP2; c++) acc[r][c] = make_float2(0.f, 0.f);

    for (int k = 0; k < K; k += 4) {
        float4 xv[8];
        #pragma unroll
        for (int r = 0; r < 8; r++)
            xv[r] = *(const float4*)&Xs[(ty * 8 + r) * K + k];

        #pragma unroll
        for (int kk = 0; kk < 4; kk++) {
            float2 wv[CP2];
            #pragma unroll
            for (int c = 0; c < CP2; c++)
                wv[c] = *(const float2*)&Ws[(k + kk) * DO + 2 * tx + 64 * c];
            #pragma unroll
            for (int r = 0; r < 8; r++) {
                float xs = (kk == 0) ? xv[r].x : (kk == 1) ? xv[r].y
                         : (kk == 2) ? xv[r].z : xv[r].w;
                #pragma unroll
                for (int c = 0; c < CP2; c++) {
                    acc[r][c].x = fmaf(xs, wv[c].x, acc[r][c].x);
                    acc[r][c].y = fmaf(xs, wv[c].y, acc[r][c].y);
                }
            }
        }
    }

    #pragma unroll
    for (int r = 0; r < 8; r++) {
        int row = bm + ty * 8 + r;
        if (row < M) {
            #pragma unroll
            for (int c = 0; c < CP2; c++) {
                float2 v = acc[r][c];
                if (BIAS) {
                    float2 bv = *(const float2*)&bias[2 * tx + 64 * c];
                    v.x += bv.x; v.y += bv.y;
                }
                size_t off = (size_t)row * DO + 2 * tx + 64 * c;
                if (HALF_OUT)
                    *(__half2*)((__half*)Y + off) = __floats2half2_rn(v.x, v.y);
                else
                    *(float2*)((float*)Y + off) = v;
            }
        }
    }
}

// ---------------------------------------------------------------------------
// Gather aggregation (fused self-loop + bias + ReLU), fp16 t input:
//   h[i,f] = relu( t[i,f]*dinv[i]^2 + sum_{s in in(i)} t[s,f]*dinv[s]*dinv[i] + b[f] )
// Each thread owns one feature PAIR; D/2 threads per node; 128 threads/block.
// ---------------------------------------------------------------------------
template <int D, int NPB>   // NPB * (D/2) == 128
__global__ void gather_kernel(const __half2* __restrict__ t2,
                              const float* __restrict__ bias,
                              float* __restrict__ h) {
    constexpr int D2 = D / 2;
    const int ln   = threadIdx.x / D2;
    const int f2   = threadIdx.x % D2;
    const int node = blockIdx.x * NPB + ln;
    if (node >= NN) return;

    const float di  = g_dinv[node];
    const int   beg = g_rowptr[node];
    const int   end = g_rowptr[node + 1];

    float2 sv = __half22float2(t2[(size_t)node * D2 + f2]);
    float ax = sv.x * di * di;          // self loop
    float ay = sv.y * di * di;

    int e = beg;
    for (; e + 4 <= end; e += 4) {
        int s0 = __ldg(&g_csrc[e]);
        int s1 = __ldg(&g_csrc[e + 1]);
        int s2 = __ldg(&g_csrc[e + 2]);
        int s3 = __ldg(&g_csrc[e + 3]);
        float n0 = __ldg(&g_dinv[s0]) * di;
        float n1 = __ldg(&g_dinv[s1]) * di;
        float n2 = __ldg(&g_dinv[s2]) * di;
        float n3 = __ldg(&g_dinv[s3]) * di;
        float2 v0 = __half22float2(t2[(size_t)s0 * D2 + f2]);
        float2 v1 = __half22float2(t2[(size_t)s1 * D2 + f2]);
        float2 v2 = __half22float2(t2[(size_t)s2 * D2 + f2]);
        float2 v3 = __half22float2(t2[(size_t)s3 * D2 + f2]);
        ax = fmaf(v0.x, n0, ax); ay = fmaf(v0.y, n0, ay);
        ax = fmaf(v1.x, n1, ax); ay = fmaf(v1.y, n1, ay);
        ax = fmaf(v2.x, n2, ax); ay = fmaf(v2.y, n2, ay);
        ax = fmaf(v3.x, n3, ax); ay = fmaf(v3.y, n3, ay);
    }
    for (; e < end; e++) {
        int s = __ldg(&g_csrc[e]);
        float n = __ldg(&g_dinv[s]) * di;
        float2 v = __half22float2(t2[(size_t)s * D2 + f2]);
        ax = fmaf(v.x, n, ax); ay = fmaf(v.y, n, ay);
    }

    float2 bv = *(const float2*)&bias[2 * f2];
    ax = fmaxf(ax + bv.x, 0.f);
    ay = fmaxf(ay + bv.y, 0.f);
    *(float2*)&h[(size_t)node * D + 2 * f2] = make_float2(ax, ay);
}

// ---------------------------------------------------------------------------
// Launch
// ---------------------------------------------------------------------------
extern "C" void kernel_launch(void* const* d_in, const int* in_sizes, int n_in,
                              void* d_out, int out_size) {
    const float* x   = (const float*)d_in[0];
    const void*  ei  = d_in[1];                  // int32 or int64 (detected)
    const float* W1  = (const float*)d_in[2];
    const float* b1  = (const float*)d_in[3];
    const float* W2  = (const float*)d_in[4];
    const float* b2  = (const float*)d_in[5];
    const float* fcW = (const float*)d_in[6];
    const float* fcb = (const float*)d_in[7];
    float*       out = (float*)d_out;

    __half2* t_ptr = nullptr;
    float*   h_ptr = nullptr;
    cudaGetSymbolAddress((void**)&t_ptr, g_t2);
    cudaGetSymbolAddress((void**)&h_ptr, g_h4);

    constexpr int SM_G1 = (DIN * DHID + 64 * DIN) * 4;    // 96 KB
    constexpr int SM_G2 = (DHID * DOUT + 64 * DHID) * 4;  // 64 KB
    constexpr int SM_G3 = (DOUT * DOUT + 64 * DOUT) * 4;  // 32 KB
    cudaFuncSetAttribute(gemm_kernel<DIN, DHID, false, true>,
                         cudaFuncAttributeMaxDynamicSharedMemorySize, SM_G1);
    cudaFuncSetAttribute(gemm_kernel<DHID, DOUT, false, true>,
                         cudaFuncAttributeMaxDynamicSharedMemorySize, SM_G2);
    cudaFuncSetAttribute(gemm_kernel<DOUT, DOUT, true, false>,
                         cudaFuncAttributeMaxDynamicSharedMemorySize, SM_G3);

    const int TB = 256;
    const int gN    = (NN + TB - 1) / TB;
    const int gE    = (NE + TB - 1) / TB;
    const int gGemm = (NN + 63) / 64;

    // --- dtype detection + CSR build + normalization ---
    detect_kernel<<<1, 1>>>(ei);
    zero_kernel<<<gN, TB>>>();
    deg_count_kernel<<<gE, TB>>>(ei);
    scan_partial_kernel<<<SCAN_G, SCAN_B>>>();
    scan_bsum_kernel<<<1, 256>>>();
    scan_final_kernel<<<SCAN_G, SCAN_B>>>();
    fill_kernel<<<gE, TB>>>(ei);

    // --- Layer 1 ---
    gemm_kernel<DIN, DHID, false, true><<<gGemm, TB, SM_G1>>>(x, W1, nullptr, t_ptr, NN);
    gather_kernel<DHID, 2><<<(NN + 1) / 2, 128>>>(t_ptr, b1, h_ptr);

    // --- Layer 2 ---
    gemm_kernel<DHID, DOUT, false, true><<<gGemm, TB, SM_G2>>>(h_ptr, W2, nullptr, t_ptr, NN);
    gather_kernel<DOUT, 4><<<(NN + 3) / 4, 128>>>(t_ptr, b2, h_ptr);

    // --- Final FC ---
    gemm_kernel<DOUT, DOUT, true, false><<<gGemm, TB, SM_G3>>>(h_ptr, fcW, fcb, out, NN);
}

// round 6
// speedup vs baseline: 1.6849x; 1.2191x over previous
#include <cuda_runtime.h>
#include <cuda_fp16.h>

// Problem constants (fixed by the reference)
#define NN   50000
#define NE   800000
#define DIN  128
#define DHID 128
#define DOUT 64

#define SCAN_B   256
#define SCAN_G   ((NN + SCAN_B - 1) / SCAN_B)   // 196

// ---------------------------------------------------------------------------
// Static device scratch (no allocation allowed)
// ---------------------------------------------------------------------------
__device__ int    g_is64;                     // 1 if edge_index is int64
__device__ int    g_deg[NN];
__device__ int    g_cur[NN];
__device__ int    g_bsum[SCAN_G];             // per-block sums for scan
__device__ int    g_rowptr[NN + 1];
__device__ int    g_csrc[NE];                 // CSR: src node per incoming edge
__device__ float  g_dinv[NN];                 // rsqrt(1 + in_degree)
__device__ uint4  g_t16[NN * DHID / 8];       // transform buffer (8 x fp16 per uint4)
__device__ float4 g_h4[NN * DHID / 4];        // aggregation buffer (fp32)

// ---------------------------------------------------------------------------
// f32x2 packed FMA helpers (Blackwell FFMA2 — only reachable via PTX)
// ---------------------------------------------------------------------------
__device__ __forceinline__ unsigned long long pack2(float x) {
    unsigned long long r;
    asm("mov.b64 %0, {%1, %2};" : "=l"(r) : "f"(x), "f"(x));
    return r;
}
__device__ __forceinline__ void fma2(unsigned long long& d,
                                     unsigned long long a, unsigned long long b) {
    asm("fma.rn.f32x2 %0, %1, %2, %0;" : "+l"(d) : "l"(a), "l"(b));
}
__device__ __forceinline__ float2 unpack2(unsigned long long v) {
    float2 f;
    asm("mov.b64 {%0, %1}, %2;" : "=f"(f.x), "=f"(f.y) : "l"(v));
    return f;
}

// ---------------------------------------------------------------------------
// Edge-index dtype detection + accessor
// ---------------------------------------------------------------------------
__global__ void detect_kernel(const void* __restrict__ ei) {
    const long long* p = (const long long*)ei;
    int ok = 1;
    for (int i = 0; i < 64; i++) {
        long long v = p[i];
        if (v < 0 || v >= NN) { ok = 0; break; }
    }
    g_is64 = ok;
}

__device__ __forceinline__ int edge_at(const void* ei, int is64, int pos) {
    if (is64) return (int)((const long long*)ei)[pos];
    return ((const int*)ei)[pos];
}

// ---------------------------------------------------------------------------
// CSR construction
// ---------------------------------------------------------------------------
__global__ void zero_kernel() {
    int i = blockIdx.x * blockDim.x + threadIdx.x;
    if (i < NN) g_deg[i] = 0;
}

__global__ void deg_count_kernel(const void* __restrict__ ei) {
    int e = blockIdx.x * blockDim.x + threadIdx.x;
    int is64 = g_is64;
    if (e < NE) {
        int dst = edge_at(ei, is64, NE + e);
        atomicAdd(&g_deg[dst], 1);
    }
}

__global__ void scan_partial_kernel() {
    __shared__ int wsum[SCAN_B / 32];
    int i = blockIdx.x * SCAN_B + threadIdx.x;
    int lane = threadIdx.x & 31, w = threadIdx.x >> 5;
    int v = (i < NN) ? g_deg[i] : 0;
    #pragma unroll
    for (int o = 16; o > 0; o >>= 1) v += __shfl_down_sync(0xffffffffu, v, o);
    if (lane == 0) wsum[w] = v;
    __syncthreads();
    if (threadIdx.x == 0) {
        int s = 0;
        #pragma unroll
        for (int k = 0; k < SCAN_B / 32; k++) s += wsum[k];
        g_bsum[blockIdx.x] = s;
    }
}

__global__ void scan_bsum_kernel() {
    __shared__ int ws[8];
    int tid = threadIdx.x, lane = tid & 31, w = tid >> 5;
    int v = (tid < SCAN_G) ? g_bsum[tid] : 0;
    int inc = v;
    #pragma unroll
    for (int o = 1; o < 32; o <<= 1) {
        int n = __shfl_up_sync(0xffffffffu, inc, o);
        if (lane >= o) inc += n;
    }
    if (lane == 31) ws[w] = inc;
    __syncthreads();
    if (w == 0 && lane < 8) {
        int s = ws[lane];
        #pragma unroll
        for (int o = 1; o < 8; o <<= 1) {
            int n = __shfl_up_sync(0xffu, s, o);
            if (lane >= o) s += n;
        }
        ws[lane] = s;
    }
    __syncthreads();
    int off = (w == 0) ? 0 : ws[w - 1];
    if (tid < SCAN_G) g_bsum[tid] = off + inc - v;      // exclusive
    if (tid == SCAN_G - 1) g_rowptr[NN] = off + inc;    // total
}

__global__ void scan_final_kernel() {
    __shared__ int wsum[SCAN_B / 32];
    int i = blockIdx.x * SCAN_B + threadIdx.x;
    int lane = threadIdx.x & 31, w = threadIdx.x >> 5;
    int v = (i < NN) ? g_deg[i] : 0;
    int inc = v;
    #pragma unroll
    for (int o = 1; o < 32; o <<= 1) {
        int n = __shfl_up_sync(0xffffffffu, inc, o);
        if (lane >= o) inc += n;
    }
    if (lane == 31) wsum[w] = inc;
    __syncthreads();
    if (w == 0 && lane < SCAN_B / 32) {
        int s = wsum[lane];
        #pragma unroll
        for (int o = 1; o < SCAN_B / 32; o <<= 1) {
            int n = __shfl_up_sync((1u << (SCAN_B / 32)) - 1u, s, o);
            if (lane >= o) s += n;
        }
        wsum[lane] = s;
    }
    __syncthreads();
    int woff = (w == 0) ? 0 : wsum[w - 1];
    if (i < NN) {
        g_rowptr[i] = g_bsum[blockIdx.x] + woff + inc - v;
        g_dinv[i]   = rsqrtf(1.0f + (float)v);
        g_cur[i]    = 0;
    }
}

__global__ void fill_kernel(const void* __restrict__ ei) {
    int e = blockIdx.x * blockDim.x + threadIdx.x;
    int is64 = g_is64;
    if (e < NE) {
        int src = edge_at(ei, is64, e);
        int dst = edge_at(ei, is64, NE + e);
        int pos = g_rowptr[dst] + atomicAdd(&g_cur[dst], 1);
        g_csrc[pos] = src;
    }
}

// ---------------------------------------------------------------------------
// GEMM: Y[M, DO] = X[M, K] @ W[K, DO]  (+ bias if BIAS)
// 64 rows/block, 256 threads, W + X tile in SMEM.
// Thread owns 8 rows x (DO/64) column PAIRS via packed f32x2 FMA.
// HALF_OUT: store __half2; else float2.
// ---------------------------------------------------------------------------
template <int K, int DO, bool BIAS, bool HALF_OUT>
__global__ void gemm_kernel(const float* __restrict__ X,
                            const float* __restrict__ W,
                            const float* __restrict__ bias,
                            void* __restrict__ Y, int M) {
    extern __shared__ float sm[];
    float* Ws = sm;            // K * DO
    float* Xs = sm + K * DO;   // 64 * K

    const int tid = threadIdx.x;
    const int bm  = blockIdx.x * 64;

    #pragma unroll 4
    for (int i = tid; i < K * DO / 4; i += 256)
        ((float4*)Ws)[i] = ((const float4*)W)[i];

    #pragma unroll 4
    for (int i = tid; i < 64 * K / 4; i += 256) {
        int row  = i / (K / 4);
        int col4 = i % (K / 4);
        float4 v = make_float4(0.f, 0.f, 0.f, 0.f);
        if (bm + row < M)
            v = ((const float4*)(X + (size_t)(bm + row) * K))[col4];
        ((float4*)Xs)[i] = v;
    }
    __syncthreads();

    const int tx = tid & 31;
    const int ty = tid >> 5;           // 0..7
    constexpr int CP2 = DO / 64;       // column pairs per thread

    unsigned long long acc[8][CP2];
    #pragma unroll
    for (int r = 0; r < 8; r++)
        #pragma unroll
        for (int c = 0; c < CP2; c++) acc[r][c] = 0ull;

    for (int k = 0; k < K; k += 4) {
        float4 xv[8];
        #pragma unroll
        for (int r = 0; r < 8; r++)
            xv[r] = *(const float4*)&Xs[(ty * 8 + r) * K + k];

        #pragma unroll
        for (int kk = 0; kk < 4; kk++) {
            unsigned long long wv[CP2];
            #pragma unroll
            for (int c = 0; c < CP2; c++)
                wv[c] = *(const unsigned long long*)&Ws[(k + kk) * DO + 2 * tx + 64 * c];
            #pragma unroll
            for (int r = 0; r < 8; r++) {
                float xs = (kk == 0) ? xv[r].x : (kk == 1) ? xv[r].y
                         : (kk == 2) ? xv[r].z : xv[r].w;
                unsigned long long xp = pack2(xs);
                #pragma unroll
                for (int c = 0; c < CP2; c++)
                    fma2(acc[r][c], xp, wv[c]);
            }
        }
    }

    #pragma unroll
    for (int r = 0; r < 8; r++) {
        int row = bm + ty * 8 + r;
        if (row < M) {
            #pragma unroll
            for (int c = 0; c < CP2; c++) {
                float2 v = unpack2(acc[r][c]);
                if (BIAS) {
                    float2 bv = *(const float2*)&bias[2 * tx + 64 * c];
                    v.x += bv.x; v.y += bv.y;
                }
                size_t off = (size_t)row * DO + 2 * tx + 64 * c;
                if (HALF_OUT)
                    *(__half2*)((__half*)Y + off) = __floats2half2_rn(v.x, v.y);
                else
                    *(float2*)((float*)Y + off) = v;
            }
        }
    }
}

// ---------------------------------------------------------------------------
// Gather aggregation (fused self-loop + bias + ReLU), fp16 t input:
//   h[i,f] = relu( t[i,f]*dinv[i]^2 + sum_{s in in(i)} t[s,f]*dinv[s]*dinv[i] + b[f] )
// Each thread owns 8 features (one uint4 = 4 half2); D/8 threads per node.
// ---------------------------------------------------------------------------
__device__ __forceinline__ void fma8(float* acc, uint4 raw, float n) {
    float2 p0 = __half22float2(*(__half2*)&raw.x);
    float2 p1 = __half22float2(*(__half2*)&raw.y);
    float2 p2 = __half22float2(*(__half2*)&raw.z);
    float2 p3 = __half22float2(*(__half2*)&raw.w);
    acc[0] = fmaf(p0.x, n, acc[0]); acc[1] = fmaf(p0.y, n, acc[1]);
    acc[2] = fmaf(p1.x, n, acc[2]); acc[3] = fmaf(p1.y, n, acc[3]);
    acc[4] = fmaf(p2.x, n, acc[4]); acc[5] = fmaf(p2.y, n, acc[5]);
    acc[6] = fmaf(p3.x, n, acc[6]); acc[7] = fmaf(p3.y, n, acc[7]);
}

template <int D, int NPB>   // NPB * (D/8) == 128
__global__ void gather_kernel(const uint4* __restrict__ t16,
                              const float* __restrict__ bias,
                              float* __restrict__ h) {
    constexpr int D8 = D / 8;
    const int ln   = threadIdx.x / D8;
    const int f8   = threadIdx.x % D8;
    const int node = blockIdx.x * NPB + ln;
    if (node >= NN) return;

    const float di  = g_dinv[node];
    const int   beg = g_rowptr[node];
    const int   end = g_rowptr[node + 1];

    float acc[8] = {0, 0, 0, 0, 0, 0, 0, 0};
    fma8(acc, t16[(size_t)node * D8 + f8], di * di);   // self loop

    int e = beg;
    for (; e + 4 <= end; e += 4) {
        int s0 = __ldg(&g_csrc[e]);
        int s1 = __ldg(&g_csrc[e + 1]);
        int s2 = __ldg(&g_csrc[e + 2]);
        int s3 = __ldg(&g_csrc[e + 3]);
        uint4 r0 = t16[(size_t)s0 * D8 + f8];
        uint4 r1 = t16[(size_t)s1 * D8 + f8];
        uint4 r2 = t16[(size_t)s2 * D8 + f8];
        uint4 r3 = t16[(size_t)s3 * D8 + f8];
        float n0 = __ldg(&g_dinv[s0]) * di;
        float n1 = __ldg(&g_dinv[s1]) * di;
        float n2 = __ldg(&g_dinv[s2]) * di;
        float n3 = __ldg(&g_dinv[s3]) * di;
        fma8(acc, r0, n0);
        fma8(acc, r1, n1);
        fma8(acc, r2, n2);
        fma8(acc, r3, n3);
    }
    for (; e < end; e++) {
        int s = __ldg(&g_csrc[e]);
        fma8(acc, t16[(size_t)s * D8 + f8], __ldg(&g_dinv[s]) * di);
    }

    float4 b0 = *(const float4*)&bias[8 * f8];
    float4 b1 = *(const float4*)&bias[8 * f8 + 4];
    float4 o0 = make_float4(fmaxf(acc[0] + b0.x, 0.f), fmaxf(acc[1] + b0.y, 0.f),
                            fmaxf(acc[2] + b0.z, 0.f), fmaxf(acc[3] + b0.w, 0.f));
    float4 o1 = make_float4(fmaxf(acc[4] + b1.x, 0.f), fmaxf(acc[5] + b1.y, 0.f),
                            fmaxf(acc[6] + b1.z, 0.f), fmaxf(acc[7] + b1.w, 0.f));
    float4* hp = (float4*)&h[(size_t)node * D + 8 * f8];
    hp[0] = o0;
    hp[1] = o1;
}

// ---------------------------------------------------------------------------
// Launch
// ---------------------------------------------------------------------------
extern "C" void kernel_launch(void* const* d_in, const int* in_sizes, int n_in,
                              void* d_out, int out_size) {
    const float* x   = (const float*)d_in[0];
    const void*  ei  = d_in[1];                  // int32 or int64 (detected)
    const float* W1  = (const float*)d_in[2];
    const float* b1  = (const float*)d_in[3];
    const float* W2  = (const float*)d_in[4];
    const float* b2  = (const float*)d_in[5];
    const float* fcW = (const float*)d_in[6];
    const float* fcb = (const float*)d_in[7];
    float*       out = (float*)d_out;

    uint4* t_ptr = nullptr;
    float* h_ptr = nullptr;
    cudaGetSymbolAddress((void**)&t_ptr, g_t16);
    cudaGetSymbolAddress((void**)&h_ptr, g_h4);

    constexpr int SM_G1 = (DIN * DHID + 64 * DIN) * 4;    // 96 KB
    constexpr int SM_G2 = (DHID * DOUT + 64 * DHID) * 4;  // 64 KB
    constexpr int SM_G3 = (DOUT * DOUT + 64 * DOUT) * 4;  // 32 KB
    cudaFuncSetAttribute(gemm_kernel<DIN, DHID, false, true>,
                         cudaFuncAttributeMaxDynamicSharedMemorySize, SM_G1);
    cudaFuncSetAttribute(gemm_kernel<DHID, DOUT, false, true>,
                         cudaFuncAttributeMaxDynamicSharedMemorySize, SM_G2);
    cudaFuncSetAttribute(gemm_kernel<DOUT, DOUT, true, false>,
                         cudaFuncAttributeMaxDynamicSharedMemorySize, SM_G3);

    const int TB = 256;
    const int gN    = (NN + TB - 1) / TB;
    const int gE    = (NE + TB - 1) / TB;
    const int gGemm = (NN + 63) / 64;

    // --- dtype detection + CSR build + normalization ---
    detect_kernel<<<1, 1>>>(ei);
    zero_kernel<<<gN, TB>>>();
    deg_count_kernel<<<gE, TB>>>(ei);
    scan_partial_kernel<<<SCAN_G, SCAN_B>>>();
    scan_bsum_kernel<<<1, 256>>>();
    scan_final_kernel<<<SCAN_G, SCAN_B>>>();
    fill_kernel<<<gE, TB>>>(ei);

    // --- Layer 1 ---
    gemm_kernel<DIN, DHID, false, true><<<gGemm, TB, SM_G1>>>(x, W1, nullptr, t_ptr, NN);
    gather_kernel<DHID, 8><<<(NN + 7) / 8, 128>>>(t_ptr, b1, h_ptr);

    // --- Layer 2 ---
    gemm_kernel<DHID, DOUT, false, true><<<gGemm, TB, SM_G2>>>(h_ptr, W2, nullptr, t_ptr, NN);
    gather_kernel<DOUT, 16><<<(NN + 15) / 16, 128>>>(t_ptr, b2, h_ptr);

    // --- Final FC ---
    gemm_kernel<DOUT, DOUT, true, false><<<gGemm, TB, SM_G3>>>(h_ptr, fcW, fcb, out, NN);
}

// round 7
// speedup vs baseline: 1.6882x; 1.0019x over previous
#include <cuda_runtime.h>
#include <cuda_fp16.h>

// Problem constants (fixed by the reference)
#define NN   50000
#define NE   800000
#define DIN  128
#define DHID 128
#define DOUT 64

#define SCAN_B   256
#define SCAN_G   ((NN + SCAN_B - 1) / SCAN_B)   // 196

// ---------------------------------------------------------------------------
// Static device scratch (no allocation allowed)
// ---------------------------------------------------------------------------
__device__ int    g_is64;                     // 1 if edge_index is int64
__device__ int    g_deg[NN];
__device__ int    g_cur[NN];
__device__ int    g_bsum[SCAN_G];             // per-block sums for scan
__device__ int    g_rowptr[NN + 1];
__device__ int2   g_edge[NE];                 // CSR: {src, norm-as-int} per in-edge
__device__ float  g_dinv[NN];                 // rsqrt(1 + in_degree)
__device__ uint4  g_t16[NN * DHID / 8];       // transform buffer (8 x fp16 per uint4)
__device__ float4 g_h4[NN * DHID / 4];        // aggregation buffer (fp32)

// ---------------------------------------------------------------------------
// f32x2 packed FMA helpers (Blackwell FFMA2 — only reachable via PTX)
// ---------------------------------------------------------------------------
__device__ __forceinline__ unsigned long long pack2(float x) {
    unsigned long long r;
    asm("mov.b64 %0, {%1, %2};" : "=l"(r) : "f"(x), "f"(x));
    return r;
}
__device__ __forceinline__ void fma2(unsigned long long& d,
                                     unsigned long long a, unsigned long long b) {
    asm("fma.rn.f32x2 %0, %1, %2, %0;" : "+l"(d) : "l"(a), "l"(b));
}
__device__ __forceinline__ float2 unpack2(unsigned long long v) {
    float2 f;
    asm("mov.b64 {%0, %1}, %2;" : "=f"(f.x), "=f"(f.y) : "l"(v));
    return f;
}

// ---------------------------------------------------------------------------
// CSR construction
// ---------------------------------------------------------------------------
// zero + fused dtype detection (block 0, thread 0)
__global__ void zero_kernel(const void* __restrict__ ei) {
    int i = blockIdx.x * blockDim.x + threadIdx.x;
    if (i < NN) g_deg[i] = 0;
    if (blockIdx.x == 0 && threadIdx.x == 0) {
        // True int64 indices are all in [0, NN); int32 data reinterpreted as
        // int64 exceeds NN unless the odd word is zero (p ~ 1e-5 per entry).
        const long long* p = (const long long*)ei;
        int ok = 1;
        for (int k = 0; k < 64; k++) {
            long long v = p[k];
            if (v < 0 || v >= NN) { ok = 0; break; }
        }
        g_is64 = ok;
    }
}

// 2 edges per thread
__global__ void deg_count_kernel(const void* __restrict__ ei) {
    int e2 = blockIdx.x * blockDim.x + threadIdx.x;   // over NE/2
    if (e2 >= NE / 2) return;
    int d0, d1;
    if (g_is64) {
        longlong2 d = ((const longlong2*)ei)[NE / 2 + e2];
        d0 = (int)d.x; d1 = (int)d.y;
    } else {
        int2 d = ((const int2*)ei)[NE / 2 + e2];
        d0 = d.x; d1 = d.y;
    }
    atomicAdd(&g_deg[d0], 1);
    atomicAdd(&g_deg[d1], 1);
}

__global__ void scan_partial_kernel() {
    __shared__ int wsum[SCAN_B / 32];
    int i = blockIdx.x * SCAN_B + threadIdx.x;
    int lane = threadIdx.x & 31, w = threadIdx.x >> 5;
    int v = (i < NN) ? g_deg[i] : 0;
    #pragma unroll
    for (int o = 16; o > 0; o >>= 1) v += __shfl_down_sync(0xffffffffu, v, o);
    if (lane == 0) wsum[w] = v;
    __syncthreads();
    if (threadIdx.x == 0) {
        int s = 0;
        #pragma unroll
        for (int k = 0; k < SCAN_B / 32; k++) s += wsum[k];
        g_bsum[blockIdx.x] = s;
    }
}

__global__ void scan_bsum_kernel() {
    __shared__ int ws[8];
    int tid = threadIdx.x, lane = tid & 31, w = tid >> 5;
    int v = (tid < SCAN_G) ? g_bsum[tid] : 0;
    int inc = v;
    #pragma unroll
    for (int o = 1; o < 32; o <<= 1) {
        int n = __shfl_up_sync(0xffffffffu, inc, o);
        if (lane >= o) inc += n;
    }
    if (lane == 31) ws[w] = inc;
    __syncthreads();
    if (w == 0 && lane < 8) {
        int s = ws[lane];
        #pragma unroll
        for (int o = 1; o < 8; o <<= 1) {
            int n = __shfl_up_sync(0xffu, s, o);
            if (lane >= o) s += n;
        }
        ws[lane] = s;
    }
    __syncthreads();
    int off = (w == 0) ? 0 : ws[w - 1];
    if (tid < SCAN_G) g_bsum[tid] = off + inc - v;      // exclusive
    if (tid == SCAN_G - 1) g_rowptr[NN] = off + inc;    // total
}

__global__ void scan_final_kernel() {
    __shared__ int wsum[SCAN_B / 32];
    int i = blockIdx.x * SCAN_B + threadIdx.x;
    int lane = threadIdx.x & 31, w = threadIdx.x >> 5;
    int v = (i < NN) ? g_deg[i] : 0;
    int inc = v;
    #pragma unroll
    for (int o = 1; o < 32; o <<= 1) {
        int n = __shfl_up_sync(0xffffffffu, inc, o);
        if (lane >= o) inc += n;
    }
    if (lane == 31) wsum[w] = inc;
    __syncthreads();
    if (w == 0 && lane < SCAN_B / 32) {
        int s = wsum[lane];
        #pragma unroll
        for (int o = 1; o < SCAN_B / 32; o <<= 1) {
            int n = __shfl_up_sync((1u << (SCAN_B / 32)) - 1u, s, o);
            if (lane >= o) s += n;
        }
        wsum[lane] = s;
    }
    __syncthreads();
    int woff = (w == 0) ? 0 : wsum[w - 1];
    if (i < NN) {
        g_rowptr[i] = g_bsum[blockIdx.x] + woff + inc - v;
        g_dinv[i]   = rsqrtf(1.0f + (float)v);
        g_cur[i]    = 0;
    }
}

// 2 edges per thread; writes packed {src, dinv[src]*dinv[dst]}
__global__ void fill_kernel(const void* __restrict__ ei) {
    int e2 = blockIdx.x * blockDim.x + threadIdx.x;   // over NE/2
    if (e2 >= NE / 2) return;
    int s0, s1, d0, d1;
    if (g_is64) {
        longlong2 s = ((const longlong2*)ei)[e2];
        longlong2 d = ((const longlong2*)ei)[NE / 2 + e2];
        s0 = (int)s.x; s1 = (int)s.y; d0 = (int)d.x; d1 = (int)d.y;
    } else {
        int2 s = ((const int2*)ei)[e2];
        int2 d = ((const int2*)ei)[NE / 2 + e2];
        s0 = s.x; s1 = s.y; d0 = d.x; d1 = d.y;
    }
    float n0 = g_dinv[s0] * g_dinv[d0];
    float n1 = g_dinv[s1] * g_dinv[d1];
    int p0 = g_rowptr[d0] + atomicAdd(&g_cur[d0], 1);
    int p1 = g_rowptr[d1] + atomicAdd(&g_cur[d1], 1);
    g_edge[p0] = make_int2(s0, __float_as_int(n0));
    g_edge[p1] = make_int2(s1, __float_as_int(n1));
}

// ---------------------------------------------------------------------------
// GEMM: Y[M, DO] = X[M, K] @ W[K, DO]  (+ bias if BIAS)
// 64 rows/block, 256 threads, W + X tile in SMEM.
// Thread owns 8 rows x (DO/64) column PAIRS via packed f32x2 FMA.
// HALF_OUT: store __half2; else float2.
// ---------------------------------------------------------------------------
template <int K, int DO, bool BIAS, bool HALF_OUT>
__global__ void gemm_kernel(const float* __restrict__ X,
                            const float* __restrict__ W,
                            const float* __restrict__ bias,
                            void* __restrict__ Y, int M) {
    extern __shared__ float sm[];
    float* Ws = sm;            // K * DO
    float* Xs = sm + K * DO;   // 64 * K

    const int tid = threadIdx.x;
    const int bm  = blockIdx.x * 64;

    #pragma unroll 4
    for (int i = tid; i < K * DO / 4; i += 256)
        ((float4*)Ws)[i] = ((const float4*)W)[i];

    #pragma unroll 4
    for (int i = tid; i < 64 * K / 4; i += 256) {
        int row  = i / (K / 4);
        int col4 = i % (K / 4);
        float4 v = make_float4(0.f, 0.f, 0.f, 0.f);
        if (bm + row < M)
            v = ((const float4*)(X + (size_t)(bm + row) * K))[col4];
        ((float4*)Xs)[i] = v;
    }
    __syncthreads();

    const int tx = tid & 31;
    const int ty = tid >> 5;           // 0..7
    constexpr int CP2 = DO / 64;       // column pairs per thread

    unsigned long long acc[8][CP2];
    #pragma unroll
    for (int r = 0; r < 8; r++)
        #pragma unroll
        for (int c = 0; c < CP2; c++) acc[r][c] = 0ull;

    for (int k = 0; k < K; k += 4) {
        float4 xv[8];
        #pragma unroll
        for (int r = 0; r < 8; r++)
            xv[r] = *(const float4*)&Xs[(ty * 8 + r) * K + k];

        #pragma unroll
        for (int kk = 0; kk < 4; kk++) {
            unsigned long long wv[CP2];
            #pragma unroll
            for (int c = 0; c < CP2; c++)
                wv[c] = *(const unsigned long long*)&Ws[(k + kk) * DO + 2 * tx + 64 * c];
            #pragma unroll
            for (int r = 0; r < 8; r++) {
                float xs = (kk == 0) ? xv[r].x : (kk == 1) ? xv[r].y
                         : (kk == 2) ? xv[r].z : xv[r].w;
                unsigned long long xp = pack2(xs);
                #pragma unroll
                for (int c = 0; c < CP2; c++)
                    fma2(acc[r][c], xp, wv[c]);
            }
        }
    }

    #pragma unroll
    for (int r = 0; r < 8; r++) {
        int row = bm + ty * 8 + r;
        if (row < M) {
            #pragma unroll
            for (int c = 0; c < CP2; c++) {
                float2 v = unpack2(acc[r][c]);
                if (BIAS) {
                    float2 bv = *(const float2*)&bias[2 * tx + 64 * c];
                    v.x += bv.x; v.y += bv.y;
                }
                size_t off = (size_t)row * DO + 2 * tx + 64 * c;
                if (HALF_OUT)
                    *(__half2*)((__half*)Y + off) = __floats2half2_rn(v.x, v.y);
                else
                    *(float2*)((float*)Y + off) = v;
            }
        }
    }
}

// ---------------------------------------------------------------------------
// Gather aggregation (fused self-loop + bias + ReLU), fp16 t input:
//   h[i,f] = relu( t[i,f]*dinv[i]^2 + sum_{s in in(i)} t[s,f]*norm(s,i) + b[f] )
// Each thread owns 8 features (one uint4 = 4 half2); D/8 threads per node.
// Edge list is pre-packed {src, norm} pairs -> single 8B LDG per edge.
// ---------------------------------------------------------------------------
__device__ __forceinline__ void fma8(float* acc, uint4 raw, float n) {
    float2 p0 = __half22float2(*(__half2*)&raw.x);
    float2 p1 = __half22float2(*(__half2*)&raw.y);
    float2 p2 = __half22float2(*(__half2*)&raw.z);
    float2 p3 = __half22float2(*(__half2*)&raw.w);
    acc[0] = fmaf(p0.x, n, acc[0]); acc[1] = fmaf(p0.y, n, acc[1]);
    acc[2] = fmaf(p1.x, n, acc[2]); acc[3] = fmaf(p1.y, n, acc[3]);
    acc[4] = fmaf(p2.x, n, acc[4]); acc[5] = fmaf(p2.y, n, acc[5]);
    acc[6] = fmaf(p3.x, n, acc[6]); acc[7] = fmaf(p3.y, n, acc[7]);
}

template <int D, int NPB>   // NPB * (D/8) == 128
__global__ void gather_kernel(const uint4* __restrict__ t16,
                              const float* __restrict__ bias,
                              float* __restrict__ h) {
    constexpr int D8 = D / 8;
    const int ln   = threadIdx.x / D8;
    const int f8   = threadIdx.x % D8;
    const int node = blockIdx.x * NPB + ln;
    if (node >= NN) return;

    const float di  = g_dinv[node];
    const int   beg = g_rowptr[node];
    const int   end = g_rowptr[node + 1];

    float acc[8] = {0, 0, 0, 0, 0, 0, 0, 0};
    fma8(acc, t16[(size_t)node * D8 + f8], di * di);   // self loop

    int e = beg;
    for (; e + 4 <= end; e += 4) {
        int2 e0 = __ldg(&g_edge[e]);
        int2 e1 = __ldg(&g_edge[e + 1]);
        int2 e2 = __ldg(&g_edge[e + 2]);
        int2 e3 = __ldg(&g_edge[e + 3]);
        uint4 r0 = t16[(size_t)e0.x * D8 + f8];
        uint4 r1 = t16[(size_t)e1.x * D8 + f8];
        uint4 r2 = t16[(size_t)e2.x * D8 + f8];
        uint4 r3 = t16[(size_t)e3.x * D8 + f8];
        fma8(acc, r0, __int_as_float(e0.y));
        fma8(acc, r1, __int_as_float(e1.y));
        fma8(acc, r2, __int_as_float(e2.y));
        fma8(acc, r3, __int_as_float(e3.y));
    }
    for (; e < end; e++) {
        int2 ev = __ldg(&g_edge[e]);
        fma8(acc, t16[(size_t)ev.x * D8 + f8], __int_as_float(ev.y));
    }

    float4 b0 = *(const float4*)&bias[8 * f8];
    float4 b1 = *(const float4*)&bias[8 * f8 + 4];
    float4 o0 = make_float4(fmaxf(acc[0] + b0.x, 0.f), fmaxf(acc[1] + b0.y, 0.f),
                            fmaxf(acc[2] + b0.z, 0.f), fmaxf(acc[3] + b0.w, 0.f));
    float4 o1 = make_float4(fmaxf(acc[4] + b1.x, 0.f), fmaxf(acc[5] + b1.y, 0.f),
                            fmaxf(acc[6] + b1.z, 0.f), fmaxf(acc[7] + b1.w, 0.f));
    float4* hp = (float4*)&h[(size_t)node * D + 8 * f8];
    hp[0] = o0;
    hp[1] = o1;
}

// ---------------------------------------------------------------------------
// Launch
// ---------------------------------------------------------------------------
extern "C" void kernel_launch(void* const* d_in, const int* in_sizes, int n_in,
                              void* d_out, int out_size) {
    const float* x   = (const float*)d_in[0];
    const void*  ei  = d_in[1];                  // int32 or int64 (detected)
    const float* W1  = (const float*)d_in[2];
    const float* b1  = (const float*)d_in[3];
    const float* W2  = (const float*)d_in[4];
    const float* b2  = (const float*)d_in[5];
    const float* fcW = (const float*)d_in[6];
    const float* fcb = (const float*)d_in[7];
    float*       out = (float*)d_out;

    uint4* t_ptr = nullptr;
    float* h_ptr = nullptr;
    cudaGetSymbolAddress((void**)&t_ptr, g_t16);
    cudaGetSymbolAddress((void**)&h_ptr, g_h4);

    constexpr int SM_G1 = (DIN * DHID + 64 * DIN) * 4;    // 96 KB
    constexpr int SM_G2 = (DHID * DOUT + 64 * DHID) * 4;  // 64 KB
    constexpr int SM_G3 = (DOUT * DOUT + 64 * DOUT) * 4;  // 32 KB
    cudaFuncSetAttribute(gemm_kernel<DIN, DHID, false, true>,
                         cudaFuncAttributeMaxDynamicSharedMemorySize, SM_G1);
    cudaFuncSetAttribute(gemm_kernel<DHID, DOUT, false, true>,
                         cudaFuncAttributeMaxDynamicSharedMemorySize, SM_G2);
    cudaFuncSetAttribute(gemm_kernel<DOUT, DOUT, true, false>,
                         cudaFuncAttributeMaxDynamicSharedMemorySize, SM_G3);

    const int TB = 256;
    const int gN    = (NN + TB - 1) / TB;
    const int gE2   = (NE / 2 + TB - 1) / TB;
    const int gGemm = (NN + 63) / 64;

    // --- CSR build + normalization (detection fused into zero) ---
    zero_kernel<<<gN, TB>>>(ei);
    deg_count_kernel<<<gE2, TB>>>(ei);
    scan_partial_kernel<<<SCAN_G, SCAN_B>>>();
    scan_bsum_kernel<<<1, 256>>>();
    scan_final_kernel<<<SCAN_G, SCAN_B>>>();
    fill_kernel<<<gE2, TB>>>(ei);

    // --- Layer 1 ---
    gemm_kernel<DIN, DHID, false, true><<<gGemm, TB, SM_G1>>>(x, W1, nullptr, t_ptr, NN);
    gather_kernel<DHID, 8><<<(NN + 7) / 8, 128>>>(t_ptr, b1, h_ptr);

    // --- Layer 2 ---
    gemm_kernel<DHID, DOUT, false, true><<<gGemm, TB, SM_G2>>>(h_ptr, W2, nullptr, t_ptr, NN);
    gather_kernel<DOUT, 16><<<(NN + 15) / 16, 128>>>(t_ptr, b2, h_ptr);

    // --- Final FC ---
    gemm_kernel<DOUT, DOUT, true, false><<<gGemm, TB, SM_G3>>>(h_ptr, fcW, fcb, out, NN);
}

// round 8
// speedup vs baseline: 1.7710x; 1.0491x over previous
#include <cuda_runtime.h>
#include <cuda_fp16.h>

// Problem constants (fixed by the reference)
#define NN   50000
#define NE   800000
#define DIN  128
#define DHID 128
#define DOUT 64

// ---------------------------------------------------------------------------
// Static device scratch (no allocation allowed)
// ---------------------------------------------------------------------------
__device__ int    g_is64;                     // 1 if edge_index is int64
__device__ int    g_total;                    // running CSR offset
__device__ int    g_deg[NN];
__device__ int    g_cur[NN];
__device__ int    g_rowbeg[NN];               // CSR range start (unordered alloc)
__device__ int2   g_edge[NE];                 // CSR: {src, norm-as-int} per in-edge
__device__ float  g_dinv[NN];                 // rsqrt(1 + in_degree)
__device__ uint4  g_t16[NN * DHID / 8];       // transform buffer (8 x fp16 per uint4)
__device__ float4 g_h4[NN * DHID / 4];        // aggregation buffer (fp32)

// ---------------------------------------------------------------------------
// f32x2 packed FMA helpers (Blackwell FFMA2 — only reachable via PTX)
// ---------------------------------------------------------------------------
__device__ __forceinline__ unsigned long long pack2(float x) {
    unsigned long long r;
    asm("mov.b64 %0, {%1, %2};" : "=l"(r) : "f"(x), "f"(x));
    return r;
}
__device__ __forceinline__ void fma2(unsigned long long& d,
                                     unsigned long long a, unsigned long long b) {
    asm("fma.rn.f32x2 %0, %1, %2, %0;" : "+l"(d) : "l"(a), "l"(b));
}
__device__ __forceinline__ float2 unpack2(unsigned long long v) {
    float2 f;
    asm("mov.b64 {%0, %1}, %2;" : "=f"(f.x), "=f"(f.y) : "l"(v));
    return f;
}

// ---------------------------------------------------------------------------
// CSR construction
// ---------------------------------------------------------------------------
// zero deg + total, fused dtype detection (block 0, thread 0)
__global__ void zero_kernel(const void* __restrict__ ei) {
    int i = blockIdx.x * blockDim.x + threadIdx.x;
    if (i < NN) g_deg[i] = 0;
    if (blockIdx.x == 0 && threadIdx.x == 0) {
        g_total = 0;
        // True int64 indices are all in [0, NN); int32 data reinterpreted as
        // int64 exceeds NN unless the odd word is zero (p ~ 1e-5 per entry).
        const long long* p = (const long long*)ei;
        int ok = 1;
        for (int k = 0; k < 64; k++) {
            long long v = p[k];
            if (v < 0 || v >= NN) { ok = 0; break; }
        }
        g_is64 = ok;
    }
}

// 2 edges per thread
__global__ void deg_count_kernel(const void* __restrict__ ei) {
    int e2 = blockIdx.x * blockDim.x + threadIdx.x;   // over NE/2
    if (e2 >= NE / 2) return;
    int d0, d1;
    if (g_is64) {
        longlong2 d = ((const longlong2*)ei)[NE / 2 + e2];
        d0 = (int)d.x; d1 = (int)d.y;
    } else {
        int2 d = ((const int2*)ei)[NE / 2 + e2];
        d0 = d.x; d1 = d.y;
    }
    atomicAdd(&g_deg[d0], 1);
    atomicAdd(&g_deg[d1], 1);
}

// Unordered CSR range allocation (replaces 3-kernel prefix scan):
// ranges only need to be disjoint, not ordered.
__global__ void alloc_kernel() {
    int i = blockIdx.x * blockDim.x + threadIdx.x;
    if (i < NN) {
        int d = g_deg[i];
        g_rowbeg[i] = atomicAdd(&g_total, d);
        g_dinv[i]   = rsqrtf(1.0f + (float)d);
        g_cur[i]    = 0;
    }
}

// 2 edges per thread; writes packed {src, dinv[src]*dinv[dst]}
__global__ void fill_kernel(const void* __restrict__ ei) {
    int e2 = blockIdx.x * blockDim.x + threadIdx.x;   // over NE/2
    if (e2 >= NE / 2) return;
    int s0, s1, d0, d1;
    if (g_is64) {
        longlong2 s = ((const longlong2*)ei)[e2];
        longlong2 d = ((const longlong2*)ei)[NE / 2 + e2];
        s0 = (int)s.x; s1 = (int)s.y; d0 = (int)d.x; d1 = (int)d.y;
    } else {
        int2 s = ((const int2*)ei)[e2];
        int2 d = ((const int2*)ei)[NE / 2 + e2];
        s0 = s.x; s1 = s.y; d0 = d.x; d1 = d.y;
    }
    float n0 = g_dinv[s0] * g_dinv[d0];
    float n1 = g_dinv[s1] * g_dinv[d1];
    int p0 = g_rowbeg[d0] + atomicAdd(&g_cur[d0], 1);
    int p1 = g_rowbeg[d1] + atomicAdd(&g_cur[d1], 1);
    g_edge[p0] = make_int2(s0, __float_as_int(n0));
    g_edge[p1] = make_int2(s1, __float_as_int(n1));
}

// ---------------------------------------------------------------------------
// GEMM: Y[M, DO] = X[M, K] @ W[K, DO]  (+ bias if BIAS)
// 64 rows/block, 256 threads, W + X tile in SMEM.
// Thread owns 8 rows x (DO/64) column PAIRS via packed f32x2 FMA.
// HALF_OUT: store __half2; else float2.
// ---------------------------------------------------------------------------
template <int K, int DO, bool BIAS, bool HALF_OUT>
__global__ void gemm_kernel(const float* __restrict__ X,
                            const float* __restrict__ W,
                            const float* __restrict__ bias,
                            void* __restrict__ Y, int M) {
    extern __shared__ float sm[];
    float* Ws = sm;            // K * DO
    float* Xs = sm + K * DO;   // 64 * K

    const int tid = threadIdx.x;
    const int bm  = blockIdx.x * 64;

    #pragma unroll 4
    for (int i = tid; i < K * DO / 4; i += 256)
        ((float4*)Ws)[i] = ((const float4*)W)[i];

    #pragma unroll 4
    for (int i = tid; i < 64 * K / 4; i += 256) {
        int row  = i / (K / 4);
        int col4 = i % (K / 4);
        float4 v = make_float4(0.f, 0.f, 0.f, 0.f);
        if (bm + row < M)
            v = ((const float4*)(X + (size_t)(bm + row) * K))[col4];
        ((float4*)Xs)[i] = v;
    }
    __syncthreads();

    const int tx = tid & 31;
    const int ty = tid >> 5;           // 0..7
    constexpr int CP2 = DO / 64;       // column pairs per thread

    unsigned long long acc[8][CP2];
    #pragma unroll
    for (int r = 0; r < 8; r++)
        #pragma unroll
        for (int c = 0; c < CP2; c++) acc[r][c] = 0ull;

    for (int k = 0; k < K; k += 4) {
        float4 xv[8];
        #pragma unroll
        for (int r = 0; r < 8; r++)
            xv[r] = *(const float4*)&Xs[(ty * 8 + r) * K + k];

        #pragma unroll
        for (int kk = 0; kk < 4; kk++) {
            unsigned long long wv[CP2];
            #pragma unroll
            for (int c = 0; c < CP2; c++)
                wv[c] = *(const unsigned long long*)&Ws[(k + kk) * DO + 2 * tx + 64 * c];
            #pragma unroll
            for (int r = 0; r < 8; r++) {
                float xs = (kk == 0) ? xv[r].x : (kk == 1) ? xv[r].y
                         : (kk == 2) ? xv[r].z : xv[r].w;
                unsigned long long xp = pack2(xs);
                #pragma unroll
                for (int c = 0; c < CP2; c++)
                    fma2(acc[r][c], xp, wv[c]);
            }
        }
    }

    #pragma unroll
    for (int r = 0; r < 8; r++) {
        int row = bm + ty * 8 + r;
        if (row < M) {
            #pragma unroll
            for (int c = 0; c < CP2; c++) {
                float2 v = unpack2(acc[r][c]);
                if (BIAS) {
                    float2 bv = *(const float2*)&bias[2 * tx + 64 * c];
                    v.x += bv.x; v.y += bv.y;
                }
                size_t off = (size_t)row * DO + 2 * tx + 64 * c;
                if (HALF_OUT)
                    *(__half2*)((__half*)Y + off) = __floats2half2_rn(v.x, v.y);
                else
                    *(float2*)((float*)Y + off) = v;
            }
        }
    }
}

// ---------------------------------------------------------------------------
// Gather aggregation (fused self-loop + bias + ReLU), fp16 t input:
//   h[i,f] = relu( t[i,f]*dinv[i]^2 + sum_{s in in(i)} t[s,f]*norm(s,i) + b[f] )
// Each thread owns 8 features (one uint4 = 4 half2); D/8 threads per node.
// Edge list is pre-packed {src, norm} pairs -> single 8B LDG per edge.
// ---------------------------------------------------------------------------
__device__ __forceinline__ void fma8(float* acc, uint4 raw, float n) {
    float2 p0 = __half22float2(*(__half2*)&raw.x);
    float2 p1 = __half22float2(*(__half2*)&raw.y);
    float2 p2 = __half22float2(*(__half2*)&raw.z);
    float2 p3 = __half22float2(*(__half2*)&raw.w);
    acc[0] = fmaf(p0.x, n, acc[0]); acc[1] = fmaf(p0.y, n, acc[1]);
    acc[2] = fmaf(p1.x, n, acc[2]); acc[3] = fmaf(p1.y, n, acc[3]);
    acc[4] = fmaf(p2.x, n, acc[4]); acc[5] = fmaf(p2.y, n, acc[5]);
    acc[6] = fmaf(p3.x, n, acc[6]); acc[7] = fmaf(p3.y, n, acc[7]);
}

template <int D, int NPB>   // NPB * (D/8) == 128
__global__ void gather_kernel(const uint4* __restrict__ t16,
                              const float* __restrict__ bias,
                              float* __restrict__ h) {
    constexpr int D8 = D / 8;
    const int ln   = threadIdx.x / D8;
    const int f8   = threadIdx.x % D8;
    const int node = blockIdx.x * NPB + ln;
    if (node >= NN) return;

    const float di  = g_dinv[node];
    const int   beg = g_rowbeg[node];
    const int   end = beg + g_deg[node];

    float acc[8] = {0, 0, 0, 0, 0, 0, 0, 0};
    fma8(acc, t16[(size_t)node * D8 + f8], di * di);   // self loop

    int e = beg;
    for (; e + 4 <= end; e += 4) {
        int2 e0 = __ldg(&g_edge[e]);
        int2 e1 = __ldg(&g_edge[e + 1]);
        int2 e2 = __ldg(&g_edge[e + 2]);
        int2 e3 = __ldg(&g_edge[e + 3]);
        uint4 r0 = t16[(size_t)e0.x * D8 + f8];
        uint4 r1 = t16[(size_t)e1.x * D8 + f8];
        uint4 r2 = t16[(size_t)e2.x * D8 + f8];
        uint4 r3 = t16[(size_t)e3.x * D8 + f8];
        fma8(acc, r0, __int_as_float(e0.y));
        fma8(acc, r1, __int_as_float(e1.y));
        fma8(acc, r2, __int_as_float(e2.y));
        fma8(acc, r3, __int_as_float(e3.y));
    }
    for (; e < end; e++) {
        int2 ev = __ldg(&g_edge[e]);
        fma8(acc, t16[(size_t)ev.x * D8 + f8], __int_as_float(ev.y));
    }

    float4 b0 = *(const float4*)&bias[8 * f8];
    float4 b1 = *(const float4*)&bias[8 * f8 + 4];
    float4 o0 = make_float4(fmaxf(acc[0] + b0.x, 0.f), fmaxf(acc[1] + b0.y, 0.f),
                            fmaxf(acc[2] + b0.z, 0.f), fmaxf(acc[3] + b0.w, 0.f));
    float4 o1 = make_float4(fmaxf(acc[4] + b1.x, 0.f), fmaxf(acc[5] + b1.y, 0.f),
                            fmaxf(acc[6] + b1.z, 0.f), fmaxf(acc[7] + b1.w, 0.f));
    float4* hp = (float4*)&h[(size_t)node * D + 8 * f8];
    hp[0] = o0;
    hp[1] = o1;
}

// ---------------------------------------------------------------------------
// Launch: CSR build (default stream) overlapped with GEMM1 (side stream)
// ---------------------------------------------------------------------------
extern "C" void kernel_launch(void* const* d_in, const int* in_sizes, int n_in,
                              void* d_out, int out_size) {
    const float* x   = (const float*)d_in[0];
    const void*  ei  = d_in[1];                  // int32 or int64 (detected)
    const float* W1  = (const float*)d_in[2];
    const float* b1  = (const float*)d_in[3];
    const float* W2  = (const float*)d_in[4];
    const float* b2  = (const float*)d_in[5];
    const float* fcW = (const float*)d_in[6];
    const float* fcb = (const float*)d_in[7];
    float*       out = (float*)d_out;

    uint4* t_ptr = nullptr;
    float* h_ptr = nullptr;
    cudaGetSymbolAddress((void**)&t_ptr, g_t16);
    cudaGetSymbolAddress((void**)&h_ptr, g_h4);

    constexpr int SM_G1 = (DIN * DHID + 64 * DIN) * 4;    // 96 KB
    constexpr int SM_G2 = (DHID * DOUT + 64 * DHID) * 4;  // 64 KB
    constexpr int SM_G3 = (DOUT * DOUT + 64 * DOUT) * 4;  // 32 KB

    static cudaStream_t s2 = nullptr;
    static cudaEvent_t  evFork = nullptr, evJoin = nullptr;
    if (!s2) {
        cudaFuncSetAttribute(gemm_kernel<DIN, DHID, false, true>,
                             cudaFuncAttributeMaxDynamicSharedMemorySize, SM_G1);
        cudaFuncSetAttribute(gemm_kernel<DHID, DOUT, false, true>,
                             cudaFuncAttributeMaxDynamicSharedMemorySize, SM_G2);
        cudaFuncSetAttribute(gemm_kernel<DOUT, DOUT, true, false>,
                             cudaFuncAttributeMaxDynamicSharedMemorySize, SM_G3);
        cudaStreamCreateWithFlags(&s2, cudaStreamNonBlocking);
        cudaEventCreateWithFlags(&evFork, cudaEventDisableTiming);
        cudaEventCreateWithFlags(&evJoin, cudaEventDisableTiming);
    }

    const int TB = 256;
    const int gN    = (NN + TB - 1) / TB;
    const int gE2   = (NE / 2 + TB - 1) / TB;
    const int gGemm = (NN + 63) / 64;

    // --- Fork: GEMM1 on side stream (depends only on x, W1) ---
    cudaEventRecord(evFork, 0);
    cudaStreamWaitEvent(s2, evFork, 0);
    gemm_kernel<DIN, DHID, false, true><<<gGemm, TB, SM_G1, s2>>>(x, W1, nullptr, t_ptr, NN);
    cudaEventRecord(evJoin, s2);

    // --- CSR build + normalization on default stream (parallel with GEMM1) ---
    zero_kernel<<<gN, TB>>>(ei);
    deg_count_kernel<<<gE2, TB>>>(ei);
    alloc_kernel<<<gN, TB>>>();
    fill_kernel<<<gE2, TB>>>(ei);

    // --- Join: gather1 needs both CSR and t ---
    cudaStreamWaitEvent(0, evJoin, 0);
    gather_kernel<DHID, 8><<<(NN + 7) / 8, 128>>>(t_ptr, b1, h_ptr);

    // --- Layer 2 ---
    gemm_kernel<DHID, DOUT, false, true><<<gGemm, TB, SM_G2>>>(h_ptr, W2, nullptr, t_ptr, NN);
    gather_kernel<DOUT, 16><<<(NN + 15) / 16, 128>>>(t_ptr, b2, h_ptr);

    // --- Final FC ---
    gemm_kernel<DOUT, DOUT, true, false><<<gGemm, TB, SM_G3>>>(h_ptr, fcW, fcb, out, NN);
}